// round 15
// baseline (speedup 1.0000x reference)
#include <cuda_runtime.h>
#include <cuda_bf16.h>
#include <cuda_fp16.h>

#define N_NODES 100000
#define N_EDGES 1600000
#define HID 64
#define FEAT 128
#define NB 64
#define EPS 1e-5f

// ---------------- scratch (static device globals; no allocs) ----------------
__device__ float    g_deg[N_NODES];
__device__ __half   g_h1h[N_NODES * HID];   // fp16 messages, layer1
__device__ __half   g_h2h[N_NODES * HID];   // fp16 messages, layer2
__device__ float    g_acc1[N_NODES * HID];
__device__ float    g_sum[4 * HID];      // [sum1, sq1, sum2, sq2]
__device__ float    g_bnsc[HID];         // layer1 BN scale
__device__ float    g_bnsh[HID];         // layer1 BN shift
__device__ unsigned g_gx[NB * HID];      // final pooled features (float bits)
__device__ unsigned g_mxe[NB * HID];     // segment max (ordered-uint encoding)
__device__ unsigned g_mne[NB * HID];     // segment min (ordered-uint encoding)
// CSR build
__device__ int      g_cnt[N_NODES];
__device__ int      g_start[N_NODES + 1];
__device__ int      g_cursor[N_NODES];
__device__ int2     g_edge[N_EDGES];     // interleaved {src row, norm bits}

// order-preserving float<->uint encoding (total order incl. negatives)
__device__ __forceinline__ unsigned encf(float f) {
    unsigned u = __float_as_uint(f);
    return (u >> 31) ? ~u : (u | 0x80000000u);
}
__device__ __forceinline__ float decf(unsigned u) {
    return (u & 0x80000000u) ? __uint_as_float(u & 0x7fffffffu)
                             : __uint_as_float(~u);
}

// ---------------- init -------------------------------------------------------
__global__ void init_kernel() {
    int i = blockIdx.x * 256 + threadIdx.x;
    if (i < N_NODES) { g_deg[i] = 1.0f; g_cnt[i] = 0; g_cursor[i] = 0; }
    if (i < 4 * HID) g_sum[i] = 0.0f;
    if (i < NB * HID) { g_mxe[i] = 0u; g_mne[i] = 0xFFFFFFFFu; }
    if (i == 0) g_start[N_NODES] = N_EDGES;
}

// ---------------- degree: deg[c] += w ; hist: cnt[c]++ ----------------------
__global__ void deg_kernel(const int* __restrict__ col, const float* __restrict__ w) {
    int e = blockIdx.x * 256 + threadIdx.x;
    if (e < N_EDGES) {
        int c = col[e];
        atomicAdd(&g_deg[c], w[e]);
        atomicAdd(&g_cnt[c], 1);
    }
}

// ---------------- single-block exclusive scan g_cnt -> g_start --------------
#define SCH 98   // ceil(100000/1024)
__global__ void scan_kernel() {
    __shared__ int part[1024];
    int tid = threadIdx.x;
    int lo = tid * SCH;
    int hi = min(lo + SCH, N_NODES);
    int s = 0;
    for (int i = lo; i < hi; i++) s += g_cnt[i];
    part[tid] = s;
    __syncthreads();
    for (int d = 1; d < 1024; d <<= 1) {
        int t = (tid >= d) ? part[tid - d] : 0;
        __syncthreads();
        part[tid] += t;
        __syncthreads();
    }
    int run = part[tid] - s;   // exclusive prefix of this chunk
    for (int i = lo; i < hi; i++) {
        int c = g_cnt[i];
        g_start[i] = run;
        run += c;
    }
}

// ---------------- fill CSR: interleaved (row, norm) record ------------------
__global__ void fill_kernel(const int* __restrict__ row, const int* __restrict__ col,
                            const float* __restrict__ w) {
    int e = blockIdx.x * 256 + threadIdx.x;
    if (e >= N_EDGES) return;
    int c = col[e];
    int r = row[e];
    int p = atomicAdd(&g_cursor[c], 1);
    float nm = w[e] * rsqrtf(g_deg[r] * g_deg[c]);
    g_edge[g_start[c] + p] = make_int2(r, __float_as_int(nm));
}

// ---------------- gemm1: h1 = x @ W1 (fp16 only) ----------------------------
#define PP 68
__global__ void gemm1_kernel(const float* __restrict__ X, const float* __restrict__ W) {
    __shared__ float Xs[64 * PP];   // 17.4 KB
    __shared__ float Wt[64 * PP];   // 17.4 KB
    const int tid = threadIdx.x;
    const int cg = tid & 15;
    const int rg = tid >> 4;
    const int rbase = blockIdx.x * 64;

    float acc[4][4];
    #pragma unroll
    for (int i = 0; i < 4; i++)
        #pragma unroll
        for (int j = 0; j < 4; j++) acc[i][j] = 0.0f;

    #pragma unroll
    for (int kc = 0; kc < FEAT; kc += 64) {
        #pragma unroll
        for (int s = 0; s < 4; s++) {
            int t = tid + s * 256;
            int r = t >> 4, k4 = t & 15;
            int gr = rbase + r;
            if (gr >= N_NODES) gr = N_NODES - 1;
            *(float4*)&Xs[r * PP + k4 * 4] =
                *(const float4*)&X[(size_t)gr * FEAT + kc + k4 * 4];
        }
        #pragma unroll
        for (int s = 0; s < 16; s++) {
            int t = tid + s * 256;
            int k = t >> 6, j = t & 63;
            Wt[j * PP + k] = W[(kc + k) * HID + j];
        }
        __syncthreads();

        #pragma unroll 4
        for (int k0 = 0; k0 < 64; k0 += 4) {
            float4 xv[4];
            #pragma unroll
            for (int i = 0; i < 4; i++)
                xv[i] = *(const float4*)&Xs[(rg + 16 * i) * PP + k0];
            #pragma unroll
            for (int j = 0; j < 4; j++) {
                float4 wv = *(const float4*)&Wt[(cg + 16 * j) * PP + k0];
                #pragma unroll
                for (int i = 0; i < 4; i++) {
                    acc[i][j] += xv[i].x * wv.x; acc[i][j] += xv[i].y * wv.y;
                    acc[i][j] += xv[i].z * wv.z; acc[i][j] += xv[i].w * wv.w;
                }
            }
        }
        __syncthreads();
    }

    #pragma unroll
    for (int i = 0; i < 4; i++) {
        int r = rbase + rg + 16 * i;
        if (r < N_NODES) {
            #pragma unroll
            for (int j = 0; j < 4; j++)
                g_h1h[(size_t)r * HID + cg + 16 * j] = __float2half_rn(acc[i][j]);
        }
    }
}

// ---------------- bnprep: layer1 BN scale/shift from g_sum ------------------
__global__ void bnprep_kernel(const float* __restrict__ gamma, const float* __restrict__ beta) {
    int j = threadIdx.x;   // 64 threads
    float m   = g_sum[j] * (1.0f / N_NODES);
    float var = g_sum[HID + j] * (1.0f / N_NODES) - m * m;
    float inv = rsqrtf(var + EPS);
    float sc = inv * gamma[j];
    g_bnsc[j] = sc;
    g_bnsh[j] = beta[j] - m * sc;
}

// ---------------- gemm2: h2 = relu(bn(acc1)) @ W2 (fp16 only) ---------------
__global__ void gemm2_kernel(const float* __restrict__ W) {
    __shared__ float Xs[64 * PP];
    __shared__ float Wt[64 * PP];
    const int tid = threadIdx.x;
    const int cg = tid & 15;
    const int rg = tid >> 4;
    const int rbase = blockIdx.x * 64;

    // stage X: BN+ReLU fused
    #pragma unroll
    for (int s = 0; s < 4; s++) {
        int t = tid + s * 256;
        int r = t >> 4, k4 = t & 15;
        int gr = rbase + r;
        if (gr >= N_NODES) gr = N_NODES - 1;
        float4 v = *(const float4*)&g_acc1[(size_t)gr * HID + k4 * 4];
        float4 sc = *(const float4*)&g_bnsc[k4 * 4];
        float4 sh = *(const float4*)&g_bnsh[k4 * 4];
        v.x = fmaxf(fmaf(v.x, sc.x, sh.x), 0.f);
        v.y = fmaxf(fmaf(v.y, sc.y, sh.y), 0.f);
        v.z = fmaxf(fmaf(v.z, sc.z, sh.z), 0.f);
        v.w = fmaxf(fmaf(v.w, sc.w, sh.w), 0.f);
        *(float4*)&Xs[r * PP + k4 * 4] = v;
    }
    #pragma unroll
    for (int s = 0; s < 16; s++) {
        int t = tid + s * 256;
        int k = t >> 6, j = t & 63;
        Wt[j * PP + k] = W[k * HID + j];
    }
    __syncthreads();

    float acc[4][4];
    #pragma unroll
    for (int i = 0; i < 4; i++)
        #pragma unroll
        for (int j = 0; j < 4; j++) acc[i][j] = 0.0f;

    #pragma unroll 4
    for (int k0 = 0; k0 < HID; k0 += 4) {
        float4 xv[4];
        #pragma unroll
        for (int i = 0; i < 4; i++)
            xv[i] = *(const float4*)&Xs[(rg + 16 * i) * PP + k0];
        #pragma unroll
        for (int j = 0; j < 4; j++) {
            float4 wv = *(const float4*)&Wt[(cg + 16 * j) * PP + k0];
            #pragma unroll
            for (int i = 0; i < 4; i++) {
                acc[i][j] += xv[i].x * wv.x; acc[i][j] += xv[i].y * wv.y;
                acc[i][j] += xv[i].z * wv.z; acc[i][j] += xv[i].w * wv.w;
            }
        }
    }

    #pragma unroll
    for (int i = 0; i < 4; i++) {
        int r = rbase + rg + 16 * i;
        if (r < N_NODES) {
            #pragma unroll
            for (int j = 0; j < 4; j++)
                g_h2h[(size_t)r * HID + cg + 16 * j] = __float2half_rn(acc[i][j]);
        }
    }
}

// ---------------- gather: self-loop + messages + BN stats (+max/min L2) -----
// 256 thr = 16 nodes x 16 slices; slice p covers cols p*4..p*4+3 (8 B loads).
// layer 0: writes g_acc1. layer 1: no acc write; per-(graph,col) max/min
// atomics instead (BN affine + ReLU monotone => pooling commutes).
__global__ void gather_kernel(int layer, const int* __restrict__ batch) {
    const __half* h = layer ? g_h2h : g_h1h;
    __shared__ float ssum[16 * HID];
    __shared__ float ssq[16 * HID];
    __shared__ int   sbat[16];
    int ng = threadIdx.x >> 4;
    int p = threadIdx.x & 15;
    int node = blockIdx.x * 16 + ng;
    if (layer && threadIdx.x >= 128 && threadIdx.x < 144)
        sbat[threadIdx.x - 128] = batch[blockIdx.x * 16 + (threadIdx.x - 128)];
    // self-loop term: h[node] / deg[node]
    float invd = 1.0f / g_deg[node];
    __half2 s0 = *(const __half2*)&h[(size_t)node * HID + p * 4];
    __half2 s1 = *(const __half2*)&h[(size_t)node * HID + p * 4 + 2];
    float2 sf0 = __half22float2(s0), sf1 = __half22float2(s1);
    float4 a = make_float4(sf0.x * invd, sf0.y * invd, sf1.x * invd, sf1.y * invd);
    int i = g_start[node];
    int t = g_start[node + 1];
    for (; i + 3 < t; i += 4) {
        int2 e0 = g_edge[i],     e1 = g_edge[i + 1];
        int2 e2 = g_edge[i + 2], e3 = g_edge[i + 3];
        __half2 a0 = *(const __half2*)&h[(size_t)e0.x * HID + p * 4];
        __half2 b0 = *(const __half2*)&h[(size_t)e0.x * HID + p * 4 + 2];
        __half2 a1 = *(const __half2*)&h[(size_t)e1.x * HID + p * 4];
        __half2 b1 = *(const __half2*)&h[(size_t)e1.x * HID + p * 4 + 2];
        __half2 a2 = *(const __half2*)&h[(size_t)e2.x * HID + p * 4];
        __half2 b2 = *(const __half2*)&h[(size_t)e2.x * HID + p * 4 + 2];
        __half2 a3 = *(const __half2*)&h[(size_t)e3.x * HID + p * 4];
        __half2 b3 = *(const __half2*)&h[(size_t)e3.x * HID + p * 4 + 2];
        float n0 = __int_as_float(e0.y), n1 = __int_as_float(e1.y);
        float n2 = __int_as_float(e2.y), n3 = __int_as_float(e3.y);
        float2 f;
        f = __half22float2(a0); a.x += f.x * n0; a.y += f.y * n0;
        f = __half22float2(b0); a.z += f.x * n0; a.w += f.y * n0;
        f = __half22float2(a1); a.x += f.x * n1; a.y += f.y * n1;
        f = __half22float2(b1); a.z += f.x * n1; a.w += f.y * n1;
        f = __half22float2(a2); a.x += f.x * n2; a.y += f.y * n2;
        f = __half22float2(b2); a.z += f.x * n2; a.w += f.y * n2;
        f = __half22float2(a3); a.x += f.x * n3; a.y += f.y * n3;
        f = __half22float2(b3); a.z += f.x * n3; a.w += f.y * n3;
    }
    for (; i < t; i++) {
        int2 e0 = g_edge[i];
        float n0 = __int_as_float(e0.y);
        __half2 u0 = *(const __half2*)&h[(size_t)e0.x * HID + p * 4];
        __half2 u1 = *(const __half2*)&h[(size_t)e0.x * HID + p * 4 + 2];
        float2 f0 = __half22float2(u0), f1 = __half22float2(u1);
        a.x += f0.x * n0; a.y += f0.y * n0; a.z += f1.x * n0; a.w += f1.y * n0;
    }
    if (!layer)
        *(float4*)(g_acc1 + (size_t)node * HID + p * 4) = a;
    // share raw values + squares
    ssum[ng * HID + p * 4 + 0] = a.x; ssq[ng * HID + p * 4 + 0] = a.x * a.x;
    ssum[ng * HID + p * 4 + 1] = a.y; ssq[ng * HID + p * 4 + 1] = a.y * a.y;
    ssum[ng * HID + p * 4 + 2] = a.z; ssq[ng * HID + p * 4 + 2] = a.z * a.z;
    ssum[ng * HID + p * 4 + 3] = a.w; ssq[ng * HID + p * 4 + 3] = a.w * a.w;
    __syncthreads();
    float* sums = g_sum + layer * 2 * HID;
    if (threadIdx.x < 64) {
        int j = threadIdx.x;
        float s = 0.f;
        #pragma unroll
        for (int r = 0; r < 16; r++) s += ssum[r * HID + j];
        atomicAdd(&sums[j], s);
        if (layer) {   // segment max with run-length compression (sorted batch)
            int curb = sbat[0];
            float mx = ssum[j];
            #pragma unroll
            for (int r = 1; r < 16; r++) {
                int b = sbat[r];
                float v = ssum[r * HID + j];
                if (b != curb) {
                    atomicMax(&g_mxe[curb * HID + j], encf(mx));
                    curb = b; mx = v;
                } else {
                    mx = fmaxf(mx, v);
                }
            }
            atomicMax(&g_mxe[curb * HID + j], encf(mx));
        }
    } else if (threadIdx.x < 128) {
        int j = threadIdx.x - 64;
        float q = 0.f;
        #pragma unroll
        for (int r = 0; r < 16; r++) q += ssq[r * HID + j];
        atomicAdd(&sums[HID + j], q);
        if (layer) {   // segment min
            int curb = sbat[0];
            float mn = ssum[j];
            #pragma unroll
            for (int r = 1; r < 16; r++) {
                int b = sbat[r];
                float v = ssum[r * HID + j];
                if (b != curb) {
                    atomicMin(&g_mne[curb * HID + j], encf(mn));
                    curb = b; mn = v;
                } else {
                    mn = fminf(mn, v);
                }
            }
            atomicMin(&g_mne[curb * HID + j], encf(mn));
        }
    }
}

// ---------------- gx final: pick extremum per BN slope, apply BN+ReLU -------
__global__ void gxfinal_kernel(const float* __restrict__ gamma, const float* __restrict__ beta) {
    int idx = blockIdx.x * 256 + threadIdx.x;   // 16 blocks x 256 = 4096
    int j = idx & 63;
    float m   = g_sum[2 * HID + j] * (1.0f / N_NODES);
    float var = g_sum[3 * HID + j] * (1.0f / N_NODES) - m * m;
    float inv = rsqrtf(var + EPS);
    float sc = inv * gamma[j];
    float sh = beta[j] - m * sc;
    float v = (sc >= 0.f) ? decf(g_mxe[idx]) : decf(g_mne[idx]);
    g_gx[idx] = __float_as_uint(fmaxf(fmaf(v, sc, sh), 0.f));
}

// ---------------- head: speed enc + route enc + MLP (one block, 64 thr) -----
__global__ void head_kernel(const float* __restrict__ speed, const float* __restrict__ route,
                            const float* __restrict__ sw, const float* __restrict__ sb,
                            const float* __restrict__ sg, const float* __restrict__ sbe,
                            const float* __restrict__ cw, const float* __restrict__ cb,
                            const float* __restrict__ rg, const float* __restrict__ rbe,
                            const float* __restrict__ rw, const float* __restrict__ rb,
                            const float* __restrict__ ow1, const float* __restrict__ ob1,
                            const float* __restrict__ og, const float* __restrict__ obe,
                            const float* __restrict__ ow2, const float* __restrict__ ob2,
                            float* __restrict__ out) {
    int b = threadIdx.x;  // 64 threads
    __shared__ float s_v[NB][4];
    __shared__ float s_rc[NB][10];
    __shared__ float s_o1[NB][16];
    __shared__ float s_m[16], s_i[16];

    float sp = speed[b];
    #pragma unroll
    for (int j = 0; j < 4; j++) s_v[b][j] = sp * sw[j] + sb[j];

    const float* rt = route + b * 20;
    #pragma unroll
    for (int t = 0; t < 10; t++) {
        float a = cb[0];
        #pragma unroll
        for (int k = 0; k < 3; k++) {
            int tau = t + k - 1;
            if (tau >= 0 && tau < 10) {
                a += rt[tau * 2 + 0] * cw[k];
                a += rt[tau * 2 + 1] * cw[3 + k];
            }
        }
        s_rc[b][t] = a;
    }
    __syncthreads();

    if (b < 4) {
        float s = 0.f, q = 0.f;
        for (int i = 0; i < NB; i++) { float v = s_v[i][b]; s += v; q += v * v; }
        float m = s / NB, var = q / NB - m * m;
        s_m[b] = m; s_i[b] = rsqrtf(var + EPS);
    }
    if (b == 8) {
        float s = 0.f, q = 0.f;
        for (int i = 0; i < NB; i++)
            for (int t = 0; t < 10; t++) { float v = s_rc[i][t]; s += v; q += v * v; }
        float m = s / 640.f, var = q / 640.f - m * m;
        s_m[8] = m; s_i[8] = rsqrtf(var + EPS);
    }
    __syncthreads();

    float vj[4];
    #pragma unroll
    for (int j = 0; j < 4; j++)
        vj[j] = fmaxf((s_v[b][j] - s_m[j]) * s_i[j] * sg[j] + sbe[j], 0.f);

    float rcn[10];
    #pragma unroll
    for (int t = 0; t < 10; t++)
        rcn[t] = fmaxf((s_rc[b][t] - s_m[8]) * s_i[8] * rg[0] + rbe[0], 0.f);

    float rj[4];
    #pragma unroll
    for (int j = 0; j < 4; j++) {
        float a = rb[j];
        #pragma unroll
        for (int t = 0; t < 10; t++) a += rcn[t] * rw[t * 4 + j];
        rj[j] = a;
    }

    #pragma unroll
    for (int j = 0; j < 16; j++) {
        float a = ob1[j];
        for (int k = 0; k < HID; k++)
            a += __uint_as_float(g_gx[b * HID + k]) * ow1[k * 16 + j];
        #pragma unroll
        for (int k = 0; k < 4; k++) a += vj[k] * ow1[(HID + k) * 16 + j];
        #pragma unroll
        for (int k = 0; k < 4; k++) a += rj[k] * ow1[(HID + 4 + k) * 16 + j];
        s_o1[b][j] = a;
    }
    __syncthreads();
    if (b < 16) {
        float s = 0.f, q = 0.f;
        for (int i = 0; i < NB; i++) { float v = s_o1[i][b]; s += v; q += v * v; }
        float m = s / NB, var = q / NB - m * m;
        s_m[b] = m; s_i[b] = rsqrtf(var + EPS);
    }
    __syncthreads();
    float on[16];
    #pragma unroll
    for (int j = 0; j < 16; j++)
        on[j] = fmaxf((s_o1[b][j] - s_m[j]) * s_i[j] * og[j] + obe[j], 0.f);
    #pragma unroll
    for (int a = 0; a < 5; a++) {
        float o = ob2[a];
        #pragma unroll
        for (int j = 0; j < 16; j++) o += on[j] * ow2[j * 5 + a];
        out[b * 5 + a] = o;
    }
}

// ---------------------------------------------------------------------------
extern "C" void kernel_launch(void* const* d_in, const int* in_sizes, int n_in,
                              void* d_out, int out_size) {
    const float* x    = (const float*)d_in[0];
    const int*   ei   = (const int*)d_in[1];
    const float* ew   = (const float*)d_in[2];
    const int*   bidx = (const int*)d_in[3];
    const float* speed = (const float*)d_in[4];
    const float* route = (const float*)d_in[5];
    const float* W1 = (const float*)d_in[6];
    const float* g1 = (const float*)d_in[8];
    const float* be1 = (const float*)d_in[9];
    const float* W2 = (const float*)d_in[10];
    const float* g2 = (const float*)d_in[12];
    const float* be2 = (const float*)d_in[13];
    const float* sw  = (const float*)d_in[14];
    const float* sb  = (const float*)d_in[15];
    const float* sg  = (const float*)d_in[16];
    const float* sbe = (const float*)d_in[17];
    const float* cw  = (const float*)d_in[18];
    const float* cb  = (const float*)d_in[19];
    const float* rg  = (const float*)d_in[20];
    const float* rbe = (const float*)d_in[21];
    const float* rw  = (const float*)d_in[22];
    const float* rb  = (const float*)d_in[23];
    const float* ow1 = (const float*)d_in[24];
    const float* ob1 = (const float*)d_in[25];
    const float* og  = (const float*)d_in[26];
    const float* obe = (const float*)d_in[27];
    const float* ow2 = (const float*)d_in[28];
    const float* ob2 = (const float*)d_in[29];
    float* out = (float*)d_out;

    const int* row = ei;            // edge_index[0]
    const int* col = ei + N_EDGES;  // edge_index[1]

    init_kernel<<<(N_NODES + 255) / 256, 256>>>();
    deg_kernel<<<(N_EDGES + 255) / 256, 256>>>(col, ew);
    scan_kernel<<<1, 1024>>>();
    fill_kernel<<<(N_EDGES + 255) / 256, 256>>>(row, col, ew);

    gemm1_kernel<<<(N_NODES + 63) / 64, 256>>>(x, W1);
    gather_kernel<<<N_NODES / 16, 256>>>(0, bidx);
    bnprep_kernel<<<1, 64>>>(g1, be1);

    gemm2_kernel<<<(N_NODES + 63) / 64, 256>>>(W2);
    gather_kernel<<<N_NODES / 16, 256>>>(1, bidx);
    gxfinal_kernel<<<16, 256>>>(g2, be2);

    head_kernel<<<1, 64>>>(speed, route, sw, sb, sg, sbe, cw, cb, rg, rbe,
                           rw, rb, ow1, ob1, og, obe, ow2, ob2, out);
}

// round 16
// speedup vs baseline: 1.3943x; 1.3943x over previous
#include <cuda_runtime.h>
#include <cuda_bf16.h>
#include <cuda_fp16.h>

#define N_NODES 100000
#define N_EDGES 1600000
#define HID 64
#define FEAT 128
#define NB 64
#define EPS 1e-5f
#define NBLK 391   // ceil(N_NODES/256)

// ---------------- scratch (static device globals; no allocs) ----------------
__device__ float    g_deg[N_NODES];
__device__ __half   g_h1h[N_NODES * HID];   // fp16 messages, layer1
__device__ __half   g_h2h[N_NODES * HID];   // fp16 messages, layer2
__device__ float    g_acc1[N_NODES * HID];
__device__ float    g_sum[4 * HID];      // [sum1, sq1, sum2, sq2]
__device__ float    g_bnsc[HID];         // layer1 BN scale
__device__ float    g_bnsh[HID];         // layer1 BN shift
__device__ unsigned g_gx[NB * HID];      // final pooled features (float bits)
__device__ unsigned g_mxe[NB * HID];     // segment max (ordered-uint encoding)
__device__ unsigned g_mne[NB * HID];     // segment min (ordered-uint encoding)
// CSR build
__device__ int      g_cnt[N_NODES];
__device__ int      g_start[N_NODES + 1];
__device__ int      g_bsum[512];
__device__ int      g_cursor[N_NODES];
__device__ int2     g_edge[N_EDGES];     // interleaved {src row, norm bits}

// order-preserving float<->uint encoding (total order incl. negatives)
__device__ __forceinline__ unsigned encf(float f) {
    unsigned u = __float_as_uint(f);
    return (u >> 31) ? ~u : (u | 0x80000000u);
}
__device__ __forceinline__ float decf(unsigned u) {
    return (u & 0x80000000u) ? __uint_as_float(u & 0x7fffffffu)
                             : __uint_as_float(~u);
}

// ---------------- init -------------------------------------------------------
__global__ void init_kernel() {
    int i = blockIdx.x * 256 + threadIdx.x;
    if (i < N_NODES) { g_deg[i] = 1.0f; g_cnt[i] = 0; g_cursor[i] = 0; }
    if (i < 4 * HID) g_sum[i] = 0.0f;
    if (i < NB * HID) { g_mxe[i] = 0u; g_mne[i] = 0xFFFFFFFFu; }
    if (i == 0) g_start[N_NODES] = N_EDGES;
}

// ---------------- degree: deg[c] += w ; hist: cnt[c]++ ----------------------
__global__ void deg_kernel(const int* __restrict__ col, const float* __restrict__ w) {
    int e = blockIdx.x * 256 + threadIdx.x;
    if (e < N_EDGES) {
        int c = col[e];
        atomicAdd(&g_deg[c], w[e]);
        atomicAdd(&g_cnt[c], 1);
    }
}

// ---------------- parallel scan of g_cnt -> g_start (2 kernels) -------------
__global__ void scan1_kernel() {
    __shared__ int sm[256];
    int i = blockIdx.x * 256 + threadIdx.x;
    int v = (i < N_NODES) ? g_cnt[i] : 0;
    sm[threadIdx.x] = v;
    __syncthreads();
    #pragma unroll
    for (int d = 1; d < 256; d <<= 1) {
        int t = (threadIdx.x >= d) ? sm[threadIdx.x - d] : 0;
        __syncthreads();
        sm[threadIdx.x] += t;
        __syncthreads();
    }
    if (i < N_NODES) g_start[i] = sm[threadIdx.x] - v;   // exclusive within block
    if (threadIdx.x == 255) g_bsum[blockIdx.x] = sm[255];  // raw block total
}
// scan3: add prefix of block totals (computed in-block) to each element
__global__ void scan3_kernel() {
    __shared__ int red[256];
    int tid = threadIdx.x;
    int s = 0;
    for (int k = tid; k < blockIdx.x; k += 256) s += g_bsum[k];
    red[tid] = s;
    __syncthreads();
    #pragma unroll
    for (int d = 128; d > 0; d >>= 1) {
        if (tid < d) red[tid] += red[tid + d];
        __syncthreads();
    }
    int off = red[0];
    int i = blockIdx.x * 256 + tid;
    if (i < N_NODES) g_start[i] += off;
}

// ---------------- fill CSR: interleaved (row, norm) record ------------------
__global__ void fill_kernel(const int* __restrict__ row, const int* __restrict__ col,
                            const float* __restrict__ w) {
    int e = blockIdx.x * 256 + threadIdx.x;
    if (e >= N_EDGES) return;
    int c = col[e];
    int r = row[e];
    int p = atomicAdd(&g_cursor[c], 1);
    float nm = w[e] * rsqrtf(g_deg[r] * g_deg[c]);
    g_edge[g_start[c] + p] = make_int2(r, __float_as_int(nm));
}

// ---------------- gemm1: h1 = x @ W1 (fp16 only) ----------------------------
#define PP 68
__global__ void gemm1_kernel(const float* __restrict__ X, const float* __restrict__ W) {
    __shared__ float Xs[64 * PP];   // 17.4 KB
    __shared__ float Wt[64 * PP];   // 17.4 KB
    const int tid = threadIdx.x;
    const int cg = tid & 15;
    const int rg = tid >> 4;
    const int rbase = blockIdx.x * 64;

    float acc[4][4];
    #pragma unroll
    for (int i = 0; i < 4; i++)
        #pragma unroll
        for (int j = 0; j < 4; j++) acc[i][j] = 0.0f;

    #pragma unroll
    for (int kc = 0; kc < FEAT; kc += 64) {
        #pragma unroll
        for (int s = 0; s < 4; s++) {
            int t = tid + s * 256;
            int r = t >> 4, k4 = t & 15;
            int gr = rbase + r;
            if (gr >= N_NODES) gr = N_NODES - 1;
            *(float4*)&Xs[r * PP + k4 * 4] =
                *(const float4*)&X[(size_t)gr * FEAT + kc + k4 * 4];
        }
        #pragma unroll
        for (int s = 0; s < 16; s++) {
            int t = tid + s * 256;
            int k = t >> 6, j = t & 63;
            Wt[j * PP + k] = W[(kc + k) * HID + j];
        }
        __syncthreads();

        #pragma unroll 4
        for (int k0 = 0; k0 < 64; k0 += 4) {
            float4 xv[4];
            #pragma unroll
            for (int i = 0; i < 4; i++)
                xv[i] = *(const float4*)&Xs[(rg + 16 * i) * PP + k0];
            #pragma unroll
            for (int j = 0; j < 4; j++) {
                float4 wv = *(const float4*)&Wt[(cg + 16 * j) * PP + k0];
                #pragma unroll
                for (int i = 0; i < 4; i++) {
                    acc[i][j] += xv[i].x * wv.x; acc[i][j] += xv[i].y * wv.y;
                    acc[i][j] += xv[i].z * wv.z; acc[i][j] += xv[i].w * wv.w;
                }
            }
        }
        __syncthreads();
    }

    #pragma unroll
    for (int i = 0; i < 4; i++) {
        int r = rbase + rg + 16 * i;
        if (r < N_NODES) {
            #pragma unroll
            for (int j = 0; j < 4; j++)
                g_h1h[(size_t)r * HID + cg + 16 * j] = __float2half_rn(acc[i][j]);
        }
    }
}

// ---------------- bnprep: layer1 BN scale/shift from g_sum ------------------
__global__ void bnprep_kernel(const float* __restrict__ gamma, const float* __restrict__ beta) {
    int j = threadIdx.x;   // 64 threads
    float m   = g_sum[j] * (1.0f / N_NODES);
    float var = g_sum[HID + j] * (1.0f / N_NODES) - m * m;
    float inv = rsqrtf(var + EPS);
    float sc = inv * gamma[j];
    g_bnsc[j] = sc;
    g_bnsh[j] = beta[j] - m * sc;
}

// ---------------- gemm2: h2 = relu(bn(acc1)) @ W2 (fp16 only) ---------------
__global__ void gemm2_kernel(const float* __restrict__ W) {
    __shared__ float Xs[64 * PP];
    __shared__ float Wt[64 * PP];
    const int tid = threadIdx.x;
    const int cg = tid & 15;
    const int rg = tid >> 4;
    const int rbase = blockIdx.x * 64;

    // stage X: BN+ReLU fused
    #pragma unroll
    for (int s = 0; s < 4; s++) {
        int t = tid + s * 256;
        int r = t >> 4, k4 = t & 15;
        int gr = rbase + r;
        if (gr >= N_NODES) gr = N_NODES - 1;
        float4 v = *(const float4*)&g_acc1[(size_t)gr * HID + k4 * 4];
        float4 sc = *(const float4*)&g_bnsc[k4 * 4];
        float4 sh = *(const float4*)&g_bnsh[k4 * 4];
        v.x = fmaxf(fmaf(v.x, sc.x, sh.x), 0.f);
        v.y = fmaxf(fmaf(v.y, sc.y, sh.y), 0.f);
        v.z = fmaxf(fmaf(v.z, sc.z, sh.z), 0.f);
        v.w = fmaxf(fmaf(v.w, sc.w, sh.w), 0.f);
        *(float4*)&Xs[r * PP + k4 * 4] = v;
    }
    #pragma unroll
    for (int s = 0; s < 16; s++) {
        int t = tid + s * 256;
        int k = t >> 6, j = t & 63;
        Wt[j * PP + k] = W[k * HID + j];
    }
    __syncthreads();

    float acc[4][4];
    #pragma unroll
    for (int i = 0; i < 4; i++)
        #pragma unroll
        for (int j = 0; j < 4; j++) acc[i][j] = 0.0f;

    #pragma unroll 4
    for (int k0 = 0; k0 < HID; k0 += 4) {
        float4 xv[4];
        #pragma unroll
        for (int i = 0; i < 4; i++)
            xv[i] = *(const float4*)&Xs[(rg + 16 * i) * PP + k0];
        #pragma unroll
        for (int j = 0; j < 4; j++) {
            float4 wv = *(const float4*)&Wt[(cg + 16 * j) * PP + k0];
            #pragma unroll
            for (int i = 0; i < 4; i++) {
                acc[i][j] += xv[i].x * wv.x; acc[i][j] += xv[i].y * wv.y;
                acc[i][j] += xv[i].z * wv.z; acc[i][j] += xv[i].w * wv.w;
            }
        }
    }

    #pragma unroll
    for (int i = 0; i < 4; i++) {
        int r = rbase + rg + 16 * i;
        if (r < N_NODES) {
            #pragma unroll
            for (int j = 0; j < 4; j++)
                g_h2h[(size_t)r * HID + cg + 16 * j] = __float2half_rn(acc[i][j]);
        }
    }
}

// ---------------- gather: self-loop + messages + BN stats (+max/min L2) -----
// 256 thr = 16 nodes x 16 slices; slice p covers cols p*4..p*4+3 (8 B loads).
// layer 0: writes g_acc1. layer 1: no acc write; per-(graph,col) max/min
// atomics instead (BN affine + ReLU monotone => pooling commutes).
__global__ void gather_kernel(int layer, const int* __restrict__ batch) {
    const __half* h = layer ? g_h2h : g_h1h;
    __shared__ float ssum[16 * HID];
    __shared__ float ssq[16 * HID];
    __shared__ int   sbat[16];
    int ng = threadIdx.x >> 4;
    int p = threadIdx.x & 15;
    int node = blockIdx.x * 16 + ng;
    if (layer && threadIdx.x >= 128 && threadIdx.x < 144)
        sbat[threadIdx.x - 128] = batch[blockIdx.x * 16 + (threadIdx.x - 128)];
    // self-loop term: h[node] / deg[node]
    float invd = 1.0f / g_deg[node];
    __half2 s0 = *(const __half2*)&h[(size_t)node * HID + p * 4];
    __half2 s1 = *(const __half2*)&h[(size_t)node * HID + p * 4 + 2];
    float2 sf0 = __half22float2(s0), sf1 = __half22float2(s1);
    float4 a = make_float4(sf0.x * invd, sf0.y * invd, sf1.x * invd, sf1.y * invd);
    int i = g_start[node];
    int t = g_start[node + 1];
    for (; i + 3 < t; i += 4) {
        int2 e0 = g_edge[i],     e1 = g_edge[i + 1];
        int2 e2 = g_edge[i + 2], e3 = g_edge[i + 3];
        __half2 a0 = *(const __half2*)&h[(size_t)e0.x * HID + p * 4];
        __half2 b0 = *(const __half2*)&h[(size_t)e0.x * HID + p * 4 + 2];
        __half2 a1 = *(const __half2*)&h[(size_t)e1.x * HID + p * 4];
        __half2 b1 = *(const __half2*)&h[(size_t)e1.x * HID + p * 4 + 2];
        __half2 a2 = *(const __half2*)&h[(size_t)e2.x * HID + p * 4];
        __half2 b2 = *(const __half2*)&h[(size_t)e2.x * HID + p * 4 + 2];
        __half2 a3 = *(const __half2*)&h[(size_t)e3.x * HID + p * 4];
        __half2 b3 = *(const __half2*)&h[(size_t)e3.x * HID + p * 4 + 2];
        float n0 = __int_as_float(e0.y), n1 = __int_as_float(e1.y);
        float n2 = __int_as_float(e2.y), n3 = __int_as_float(e3.y);
        float2 f;
        f = __half22float2(a0); a.x += f.x * n0; a.y += f.y * n0;
        f = __half22float2(b0); a.z += f.x * n0; a.w += f.y * n0;
        f = __half22float2(a1); a.x += f.x * n1; a.y += f.y * n1;
        f = __half22float2(b1); a.z += f.x * n1; a.w += f.y * n1;
        f = __half22float2(a2); a.x += f.x * n2; a.y += f.y * n2;
        f = __half22float2(b2); a.z += f.x * n2; a.w += f.y * n2;
        f = __half22float2(a3); a.x += f.x * n3; a.y += f.y * n3;
        f = __half22float2(b3); a.z += f.x * n3; a.w += f.y * n3;
    }
    for (; i < t; i++) {
        int2 e0 = g_edge[i];
        float n0 = __int_as_float(e0.y);
        __half2 u0 = *(const __half2*)&h[(size_t)e0.x * HID + p * 4];
        __half2 u1 = *(const __half2*)&h[(size_t)e0.x * HID + p * 4 + 2];
        float2 f0 = __half22float2(u0), f1 = __half22float2(u1);
        a.x += f0.x * n0; a.y += f0.y * n0; a.z += f1.x * n0; a.w += f1.y * n0;
    }
    if (!layer)
        *(float4*)(g_acc1 + (size_t)node * HID + p * 4) = a;
    // share raw values + squares
    ssum[ng * HID + p * 4 + 0] = a.x; ssq[ng * HID + p * 4 + 0] = a.x * a.x;
    ssum[ng * HID + p * 4 + 1] = a.y; ssq[ng * HID + p * 4 + 1] = a.y * a.y;
    ssum[ng * HID + p * 4 + 2] = a.z; ssq[ng * HID + p * 4 + 2] = a.z * a.z;
    ssum[ng * HID + p * 4 + 3] = a.w; ssq[ng * HID + p * 4 + 3] = a.w * a.w;
    __syncthreads();
    float* sums = g_sum + layer * 2 * HID;
    if (threadIdx.x < 64) {
        int j = threadIdx.x;
        float s = 0.f;
        #pragma unroll
        for (int r = 0; r < 16; r++) s += ssum[r * HID + j];
        atomicAdd(&sums[j], s);
        if (layer) {   // segment max with run-length compression (sorted batch)
            int curb = sbat[0];
            float mx = ssum[j];
            #pragma unroll
            for (int r = 1; r < 16; r++) {
                int b = sbat[r];
                float v = ssum[r * HID + j];
                if (b != curb) {
                    atomicMax(&g_mxe[curb * HID + j], encf(mx));
                    curb = b; mx = v;
                } else {
                    mx = fmaxf(mx, v);
                }
            }
            atomicMax(&g_mxe[curb * HID + j], encf(mx));
        }
    } else if (threadIdx.x < 128) {
        int j = threadIdx.x - 64;
        float q = 0.f;
        #pragma unroll
        for (int r = 0; r < 16; r++) q += ssq[r * HID + j];
        atomicAdd(&sums[HID + j], q);
        if (layer) {   // segment min
            int curb = sbat[0];
            float mn = ssum[j];
            #pragma unroll
            for (int r = 1; r < 16; r++) {
                int b = sbat[r];
                float v = ssum[r * HID + j];
                if (b != curb) {
                    atomicMin(&g_mne[curb * HID + j], encf(mn));
                    curb = b; mn = v;
                } else {
                    mn = fminf(mn, v);
                }
            }
            atomicMin(&g_mne[curb * HID + j], encf(mn));
        }
    }
}

// ---------------- gx final: pick extremum per BN slope, apply BN+ReLU -------
__global__ void gxfinal_kernel(const float* __restrict__ gamma, const float* __restrict__ beta) {
    int idx = blockIdx.x * 256 + threadIdx.x;   // 16 blocks x 256 = 4096
    int j = idx & 63;
    float m   = g_sum[2 * HID + j] * (1.0f / N_NODES);
    float var = g_sum[3 * HID + j] * (1.0f / N_NODES) - m * m;
    float inv = rsqrtf(var + EPS);
    float sc = inv * gamma[j];
    float sh = beta[j] - m * sc;
    float v = (sc >= 0.f) ? decf(g_mxe[idx]) : decf(g_mne[idx]);
    g_gx[idx] = __float_as_uint(fmaxf(fmaf(v, sc, sh), 0.f));
}

// ---------------- head: speed enc + route enc + MLP (one block, 64 thr) -----
__global__ void head_kernel(const float* __restrict__ speed, const float* __restrict__ route,
                            const float* __restrict__ sw, const float* __restrict__ sb,
                            const float* __restrict__ sg, const float* __restrict__ sbe,
                            const float* __restrict__ cw, const float* __restrict__ cb,
                            const float* __restrict__ rg, const float* __restrict__ rbe,
                            const float* __restrict__ rw, const float* __restrict__ rb,
                            const float* __restrict__ ow1, const float* __restrict__ ob1,
                            const float* __restrict__ og, const float* __restrict__ obe,
                            const float* __restrict__ ow2, const float* __restrict__ ob2,
                            float* __restrict__ out) {
    int b = threadIdx.x;  // 64 threads
    __shared__ float s_v[NB][4];
    __shared__ float s_rc[NB][10];
    __shared__ float s_o1[NB][16];
    __shared__ float s_m[16], s_i[16];

    float sp = speed[b];
    #pragma unroll
    for (int j = 0; j < 4; j++) s_v[b][j] = sp * sw[j] + sb[j];

    const float* rt = route + b * 20;
    #pragma unroll
    for (int t = 0; t < 10; t++) {
        float a = cb[0];
        #pragma unroll
        for (int k = 0; k < 3; k++) {
            int tau = t + k - 1;
            if (tau >= 0 && tau < 10) {
                a += rt[tau * 2 + 0] * cw[k];
                a += rt[tau * 2 + 1] * cw[3 + k];
            }
        }
        s_rc[b][t] = a;
    }
    __syncthreads();

    if (b < 4) {
        float s = 0.f, q = 0.f;
        for (int i = 0; i < NB; i++) { float v = s_v[i][b]; s += v; q += v * v; }
        float m = s / NB, var = q / NB - m * m;
        s_m[b] = m; s_i[b] = rsqrtf(var + EPS);
    }
    if (b == 8) {
        float s = 0.f, q = 0.f;
        for (int i = 0; i < NB; i++)
            for (int t = 0; t < 10; t++) { float v = s_rc[i][t]; s += v; q += v * v; }
        float m = s / 640.f, var = q / 640.f - m * m;
        s_m[8] = m; s_i[8] = rsqrtf(var + EPS);
    }
    __syncthreads();

    float vj[4];
    #pragma unroll
    for (int j = 0; j < 4; j++)
        vj[j] = fmaxf((s_v[b][j] - s_m[j]) * s_i[j] * sg[j] + sbe[j], 0.f);

    float rcn[10];
    #pragma unroll
    for (int t = 0; t < 10; t++)
        rcn[t] = fmaxf((s_rc[b][t] - s_m[8]) * s_i[8] * rg[0] + rbe[0], 0.f);

    float rj[4];
    #pragma unroll
    for (int j = 0; j < 4; j++) {
        float a = rb[j];
        #pragma unroll
        for (int t = 0; t < 10; t++) a += rcn[t] * rw[t * 4 + j];
        rj[j] = a;
    }

    #pragma unroll
    for (int j = 0; j < 16; j++) {
        float a = ob1[j];
        for (int k = 0; k < HID; k++)
            a += __uint_as_float(g_gx[b * HID + k]) * ow1[k * 16 + j];
        #pragma unroll
        for (int k = 0; k < 4; k++) a += vj[k] * ow1[(HID + k) * 16 + j];
        #pragma unroll
        for (int k = 0; k < 4; k++) a += rj[k] * ow1[(HID + 4 + k) * 16 + j];
        s_o1[b][j] = a;
    }
    __syncthreads();
    if (b < 16) {
        float s = 0.f, q = 0.f;
        for (int i = 0; i < NB; i++) { float v = s_o1[i][b]; s += v; q += v * v; }
        float m = s / NB, var = q / NB - m * m;
        s_m[b] = m; s_i[b] = rsqrtf(var + EPS);
    }
    __syncthreads();
    float on[16];
    #pragma unroll
    for (int j = 0; j < 16; j++)
        on[j] = fmaxf((s_o1[b][j] - s_m[j]) * s_i[j] * og[j] + obe[j], 0.f);
    #pragma unroll
    for (int a = 0; a < 5; a++) {
        float o = ob2[a];
        #pragma unroll
        for (int j = 0; j < 16; j++) o += on[j] * ow2[j * 5 + a];
        out[b * 5 + a] = o;
    }
}

// ---------------------------------------------------------------------------
extern "C" void kernel_launch(void* const* d_in, const int* in_sizes, int n_in,
                              void* d_out, int out_size) {
    const float* x    = (const float*)d_in[0];
    const int*   ei   = (const int*)d_in[1];
    const float* ew   = (const float*)d_in[2];
    const int*   bidx = (const int*)d_in[3];
    const float* speed = (const float*)d_in[4];
    const float* route = (const float*)d_in[5];
    const float* W1 = (const float*)d_in[6];
    const float* g1 = (const float*)d_in[8];
    const float* be1 = (const float*)d_in[9];
    const float* W2 = (const float*)d_in[10];
    const float* g2 = (const float*)d_in[12];
    const float* be2 = (const float*)d_in[13];
    const float* sw  = (const float*)d_in[14];
    const float* sb  = (const float*)d_in[15];
    const float* sg  = (const float*)d_in[16];
    const float* sbe = (const float*)d_in[17];
    const float* cw  = (const float*)d_in[18];
    const float* cb  = (const float*)d_in[19];
    const float* rg  = (const float*)d_in[20];
    const float* rbe = (const float*)d_in[21];
    const float* rw  = (const float*)d_in[22];
    const float* rb  = (const float*)d_in[23];
    const float* ow1 = (const float*)d_in[24];
    const float* ob1 = (const float*)d_in[25];
    const float* og  = (const float*)d_in[26];
    const float* obe = (const float*)d_in[27];
    const float* ow2 = (const float*)d_in[28];
    const float* ob2 = (const float*)d_in[29];
    float* out = (float*)d_out;

    const int* row = ei;            // edge_index[0]
    const int* col = ei + N_EDGES;  // edge_index[1]

    init_kernel<<<(N_NODES + 255) / 256, 256>>>();
    deg_kernel<<<(N_EDGES + 255) / 256, 256>>>(col, ew);
    scan1_kernel<<<NBLK, 256>>>();
    scan3_kernel<<<NBLK, 256>>>();
    fill_kernel<<<(N_EDGES + 255) / 256, 256>>>(row, col, ew);

    gemm1_kernel<<<(N_NODES + 63) / 64, 256>>>(x, W1);
    gather_kernel<<<N_NODES / 16, 256>>>(0, bidx);
    bnprep_kernel<<<1, 64>>>(g1, be1);

    gemm2_kernel<<<(N_NODES + 63) / 64, 256>>>(W2);
    gather_kernel<<<N_NODES / 16, 256>>>(1, bidx);
    gxfinal_kernel<<<16, 256>>>(g2, be2);

    head_kernel<<<1, 64>>>(speed, route, sw, sb, sg, sbe, cw, cb, rg, rbe,
                           rw, rb, ow1, ob1, og, obe, ow2, ob2, out);
}

// round 17
// speedup vs baseline: 1.4062x; 1.0085x over previous
#include <cuda_runtime.h>
#include <cuda_bf16.h>
#include <cuda_fp16.h>

#define N_NODES 100000
#define N_EDGES 1600000
#define HID 64
#define FEAT 128
#define NB 64
#define EPS 1e-5f
#define NBLK 391   // ceil(N_NODES/256)

// ---------------- scratch (static device globals; no allocs) ----------------
__device__ float    g_deg[N_NODES];
__device__ __half   g_h1h[N_NODES * HID];   // fp16 messages, layer1
__device__ __half   g_h2h[N_NODES * HID];   // fp16 messages, layer2
__device__ float    g_acc1[N_NODES * HID];
__device__ float    g_sum[4 * HID];      // [sum1, sq1, sum2, sq2]
__device__ float    g_bnsc[HID];         // layer1 BN scale
__device__ float    g_bnsh[HID];         // layer1 BN shift
__device__ unsigned g_gx[NB * HID];      // final pooled features (float bits)
__device__ unsigned g_mxe[NB * HID];     // segment max (ordered-uint encoding)
__device__ unsigned g_mne[NB * HID];     // segment min (ordered-uint encoding)
// CSR build
__device__ int      g_cnt[N_NODES];
__device__ int      g_start[N_NODES + 1];
__device__ int      g_bsum[512];
__device__ int      g_cursor[N_NODES];
__device__ int2     g_edge[N_EDGES];     // interleaved {src row, norm bits}

// order-preserving float<->uint encoding (total order incl. negatives)
__device__ __forceinline__ unsigned encf(float f) {
    unsigned u = __float_as_uint(f);
    return (u >> 31) ? ~u : (u | 0x80000000u);
}
__device__ __forceinline__ float decf(unsigned u) {
    return (u & 0x80000000u) ? __uint_as_float(u & 0x7fffffffu)
                             : __uint_as_float(~u);
}

// ---------------- init -------------------------------------------------------
__global__ void init_kernel() {
    int i = blockIdx.x * 256 + threadIdx.x;
    if (i < N_NODES) { g_deg[i] = 1.0f; g_cnt[i] = 0; g_cursor[i] = 0; }
    if (i < 4 * HID) g_sum[i] = 0.0f;
    if (i < NB * HID) { g_mxe[i] = 0u; g_mne[i] = 0xFFFFFFFFu; }
    if (i == 0) g_start[N_NODES] = N_EDGES;
}

// ---------------- degree: deg[c] += w ; hist: cnt[c]++ ----------------------
__global__ void deg_kernel(const int* __restrict__ col, const float* __restrict__ w) {
    int e = blockIdx.x * 256 + threadIdx.x;
    if (e < N_EDGES) {
        int c = col[e];
        atomicAdd(&g_deg[c], w[e]);
        atomicAdd(&g_cnt[c], 1);
    }
}

// ---------------- parallel scan of g_cnt -> g_start (2 kernels) -------------
__global__ void scan1_kernel() {
    __shared__ int sm[256];
    int i = blockIdx.x * 256 + threadIdx.x;
    int v = (i < N_NODES) ? g_cnt[i] : 0;
    sm[threadIdx.x] = v;
    __syncthreads();
    #pragma unroll
    for (int d = 1; d < 256; d <<= 1) {
        int t = (threadIdx.x >= d) ? sm[threadIdx.x - d] : 0;
        __syncthreads();
        sm[threadIdx.x] += t;
        __syncthreads();
    }
    if (i < N_NODES) g_start[i] = sm[threadIdx.x] - v;   // exclusive within block
    if (threadIdx.x == 255) g_bsum[blockIdx.x] = sm[255];  // raw block total
}
// scan3: add prefix of block totals (computed in-block) to each element
__global__ void scan3_kernel() {
    __shared__ int red[256];
    int tid = threadIdx.x;
    int s = 0;
    for (int k = tid; k < blockIdx.x; k += 256) s += g_bsum[k];
    red[tid] = s;
    __syncthreads();
    #pragma unroll
    for (int d = 128; d > 0; d >>= 1) {
        if (tid < d) red[tid] += red[tid + d];
        __syncthreads();
    }
    int off = red[0];
    int i = blockIdx.x * 256 + tid;
    if (i < N_NODES) g_start[i] += off;
}

// ---------------- fill CSR: interleaved (row, norm) record ------------------
__global__ void fill_kernel(const int* __restrict__ row, const int* __restrict__ col,
                            const float* __restrict__ w) {
    int e = blockIdx.x * 256 + threadIdx.x;
    if (e >= N_EDGES) return;
    int c = col[e];
    int r = row[e];
    int p = atomicAdd(&g_cursor[c], 1);
    float nm = w[e] * rsqrtf(g_deg[r] * g_deg[c]);
    g_edge[g_start[c] + p] = make_int2(r, __float_as_int(nm));
}

// ---------------- gemm1: h1 = x @ W1 (fp16 only) ----------------------------
#define PP 68
__global__ void gemm1_kernel(const float* __restrict__ X, const float* __restrict__ W) {
    __shared__ float Xs[64 * PP];   // 17.4 KB
    __shared__ float Wt[64 * PP];   // 17.4 KB
    const int tid = threadIdx.x;
    const int cg = tid & 15;
    const int rg = tid >> 4;
    const int rbase = blockIdx.x * 64;

    float acc[4][4];
    #pragma unroll
    for (int i = 0; i < 4; i++)
        #pragma unroll
        for (int j = 0; j < 4; j++) acc[i][j] = 0.0f;

    #pragma unroll
    for (int kc = 0; kc < FEAT; kc += 64) {
        #pragma unroll
        for (int s = 0; s < 4; s++) {
            int t = tid + s * 256;
            int r = t >> 4, k4 = t & 15;
            int gr = rbase + r;
            if (gr >= N_NODES) gr = N_NODES - 1;
            *(float4*)&Xs[r * PP + k4 * 4] =
                *(const float4*)&X[(size_t)gr * FEAT + kc + k4 * 4];
        }
        #pragma unroll
        for (int s = 0; s < 16; s++) {
            int t = tid + s * 256;
            int k = t >> 6, j = t & 63;
            Wt[j * PP + k] = W[(kc + k) * HID + j];
        }
        __syncthreads();

        #pragma unroll 4
        for (int k0 = 0; k0 < 64; k0 += 4) {
            float4 xv[4];
            #pragma unroll
            for (int i = 0; i < 4; i++)
                xv[i] = *(const float4*)&Xs[(rg + 16 * i) * PP + k0];
            #pragma unroll
            for (int j = 0; j < 4; j++) {
                float4 wv = *(const float4*)&Wt[(cg + 16 * j) * PP + k0];
                #pragma unroll
                for (int i = 0; i < 4; i++) {
                    acc[i][j] += xv[i].x * wv.x; acc[i][j] += xv[i].y * wv.y;
                    acc[i][j] += xv[i].z * wv.z; acc[i][j] += xv[i].w * wv.w;
                }
            }
        }
        __syncthreads();
    }

    #pragma unroll
    for (int i = 0; i < 4; i++) {
        int r = rbase + rg + 16 * i;
        if (r < N_NODES) {
            #pragma unroll
            for (int j = 0; j < 4; j++)
                g_h1h[(size_t)r * HID + cg + 16 * j] = __float2half_rn(acc[i][j]);
        }
    }
}

// ---------------- bnprep: layer1 BN scale/shift from g_sum ------------------
__global__ void bnprep_kernel(const float* __restrict__ gamma, const float* __restrict__ beta) {
    int j = threadIdx.x;   // 64 threads
    float m   = g_sum[j] * (1.0f / N_NODES);
    float var = g_sum[HID + j] * (1.0f / N_NODES) - m * m;
    float inv = rsqrtf(var + EPS);
    float sc = inv * gamma[j];
    g_bnsc[j] = sc;
    g_bnsh[j] = beta[j] - m * sc;
}

// ---------------- gemm2: h2 = relu(bn(acc1)) @ W2 (fp16 only) ---------------
__global__ void gemm2_kernel(const float* __restrict__ W) {
    __shared__ float Xs[64 * PP];
    __shared__ float Wt[64 * PP];
    const int tid = threadIdx.x;
    const int cg = tid & 15;
    const int rg = tid >> 4;
    const int rbase = blockIdx.x * 64;

    // stage X: BN+ReLU fused
    #pragma unroll
    for (int s = 0; s < 4; s++) {
        int t = tid + s * 256;
        int r = t >> 4, k4 = t & 15;
        int gr = rbase + r;
        if (gr >= N_NODES) gr = N_NODES - 1;
        float4 v = *(const float4*)&g_acc1[(size_t)gr * HID + k4 * 4];
        float4 sc = *(const float4*)&g_bnsc[k4 * 4];
        float4 sh = *(const float4*)&g_bnsh[k4 * 4];
        v.x = fmaxf(fmaf(v.x, sc.x, sh.x), 0.f);
        v.y = fmaxf(fmaf(v.y, sc.y, sh.y), 0.f);
        v.z = fmaxf(fmaf(v.z, sc.z, sh.z), 0.f);
        v.w = fmaxf(fmaf(v.w, sc.w, sh.w), 0.f);
        *(float4*)&Xs[r * PP + k4 * 4] = v;
    }
    #pragma unroll
    for (int s = 0; s < 16; s++) {
        int t = tid + s * 256;
        int k = t >> 6, j = t & 63;
        Wt[j * PP + k] = W[k * HID + j];
    }
    __syncthreads();

    float acc[4][4];
    #pragma unroll
    for (int i = 0; i < 4; i++)
        #pragma unroll
        for (int j = 0; j < 4; j++) acc[i][j] = 0.0f;

    #pragma unroll 4
    for (int k0 = 0; k0 < HID; k0 += 4) {
        float4 xv[4];
        #pragma unroll
        for (int i = 0; i < 4; i++)
            xv[i] = *(const float4*)&Xs[(rg + 16 * i) * PP + k0];
        #pragma unroll
        for (int j = 0; j < 4; j++) {
            float4 wv = *(const float4*)&Wt[(cg + 16 * j) * PP + k0];
            #pragma unroll
            for (int i = 0; i < 4; i++) {
                acc[i][j] += xv[i].x * wv.x; acc[i][j] += xv[i].y * wv.y;
                acc[i][j] += xv[i].z * wv.z; acc[i][j] += xv[i].w * wv.w;
            }
        }
    }

    #pragma unroll
    for (int i = 0; i < 4; i++) {
        int r = rbase + rg + 16 * i;
        if (r < N_NODES) {
            #pragma unroll
            for (int j = 0; j < 4; j++)
                g_h2h[(size_t)r * HID + cg + 16 * j] = __float2half_rn(acc[i][j]);
        }
    }
}

// ---------------- gather: self-loop + messages + BN stats (+max/min L2) -----
__global__ void gather_kernel(int layer, const int* __restrict__ batch) {
    const __half* h = layer ? g_h2h : g_h1h;
    __shared__ float ssum[16 * HID];
    __shared__ float ssq[16 * HID];
    __shared__ int   sbat[16];
    int ng = threadIdx.x >> 4;
    int p = threadIdx.x & 15;
    int node = blockIdx.x * 16 + ng;
    if (layer && threadIdx.x >= 128 && threadIdx.x < 144)
        sbat[threadIdx.x - 128] = batch[blockIdx.x * 16 + (threadIdx.x - 128)];
    // self-loop term: h[node] / deg[node]
    float invd = 1.0f / g_deg[node];
    __half2 s0 = *(const __half2*)&h[(size_t)node * HID + p * 4];
    __half2 s1 = *(const __half2*)&h[(size_t)node * HID + p * 4 + 2];
    float2 sf0 = __half22float2(s0), sf1 = __half22float2(s1);
    float4 a = make_float4(sf0.x * invd, sf0.y * invd, sf1.x * invd, sf1.y * invd);
    int i = g_start[node];
    int t = g_start[node + 1];
    for (; i + 3 < t; i += 4) {
        int2 e0 = g_edge[i],     e1 = g_edge[i + 1];
        int2 e2 = g_edge[i + 2], e3 = g_edge[i + 3];
        __half2 a0 = *(const __half2*)&h[(size_t)e0.x * HID + p * 4];
        __half2 b0 = *(const __half2*)&h[(size_t)e0.x * HID + p * 4 + 2];
        __half2 a1 = *(const __half2*)&h[(size_t)e1.x * HID + p * 4];
        __half2 b1 = *(const __half2*)&h[(size_t)e1.x * HID + p * 4 + 2];
        __half2 a2 = *(const __half2*)&h[(size_t)e2.x * HID + p * 4];
        __half2 b2 = *(const __half2*)&h[(size_t)e2.x * HID + p * 4 + 2];
        __half2 a3 = *(const __half2*)&h[(size_t)e3.x * HID + p * 4];
        __half2 b3 = *(const __half2*)&h[(size_t)e3.x * HID + p * 4 + 2];
        float n0 = __int_as_float(e0.y), n1 = __int_as_float(e1.y);
        float n2 = __int_as_float(e2.y), n3 = __int_as_float(e3.y);
        float2 f;
        f = __half22float2(a0); a.x += f.x * n0; a.y += f.y * n0;
        f = __half22float2(b0); a.z += f.x * n0; a.w += f.y * n0;
        f = __half22float2(a1); a.x += f.x * n1; a.y += f.y * n1;
        f = __half22float2(b1); a.z += f.x * n1; a.w += f.y * n1;
        f = __half22float2(a2); a.x += f.x * n2; a.y += f.y * n2;
        f = __half22float2(b2); a.z += f.x * n2; a.w += f.y * n2;
        f = __half22float2(a3); a.x += f.x * n3; a.y += f.y * n3;
        f = __half22float2(b3); a.z += f.x * n3; a.w += f.y * n3;
    }
    for (; i < t; i++) {
        int2 e0 = g_edge[i];
        float n0 = __int_as_float(e0.y);
        __half2 u0 = *(const __half2*)&h[(size_t)e0.x * HID + p * 4];
        __half2 u1 = *(const __half2*)&h[(size_t)e0.x * HID + p * 4 + 2];
        float2 f0 = __half22float2(u0), f1 = __half22float2(u1);
        a.x += f0.x * n0; a.y += f0.y * n0; a.z += f1.x * n0; a.w += f1.y * n0;
    }
    if (!layer)
        *(float4*)(g_acc1 + (size_t)node * HID + p * 4) = a;
    // share raw values + squares
    ssum[ng * HID + p * 4 + 0] = a.x; ssq[ng * HID + p * 4 + 0] = a.x * a.x;
    ssum[ng * HID + p * 4 + 1] = a.y; ssq[ng * HID + p * 4 + 1] = a.y * a.y;
    ssum[ng * HID + p * 4 + 2] = a.z; ssq[ng * HID + p * 4 + 2] = a.z * a.z;
    ssum[ng * HID + p * 4 + 3] = a.w; ssq[ng * HID + p * 4 + 3] = a.w * a.w;
    __syncthreads();
    float* sums = g_sum + layer * 2 * HID;
    if (threadIdx.x < 64) {
        int j = threadIdx.x;
        float s = 0.f;
        #pragma unroll
        for (int r = 0; r < 16; r++) s += ssum[r * HID + j];
        atomicAdd(&sums[j], s);
        if (layer) {   // segment max with run-length compression (sorted batch)
            int curb = sbat[0];
            float mx = ssum[j];
            #pragma unroll
            for (int r = 1; r < 16; r++) {
                int b = sbat[r];
                float v = ssum[r * HID + j];
                if (b != curb) {
                    atomicMax(&g_mxe[curb * HID + j], encf(mx));
                    curb = b; mx = v;
                } else {
                    mx = fmaxf(mx, v);
                }
            }
            atomicMax(&g_mxe[curb * HID + j], encf(mx));
        }
    } else if (threadIdx.x < 128) {
        int j = threadIdx.x - 64;
        float q = 0.f;
        #pragma unroll
        for (int r = 0; r < 16; r++) q += ssq[r * HID + j];
        atomicAdd(&sums[HID + j], q);
        if (layer) {   // segment min
            int curb = sbat[0];
            float mn = ssum[j];
            #pragma unroll
            for (int r = 1; r < 16; r++) {
                int b = sbat[r];
                float v = ssum[r * HID + j];
                if (b != curb) {
                    atomicMin(&g_mne[curb * HID + j], encf(mn));
                    curb = b; mn = v;
                } else {
                    mn = fminf(mn, v);
                }
            }
            atomicMin(&g_mne[curb * HID + j], encf(mn));
        }
    }
}

// ---------------- gx final: pick extremum per BN slope, apply BN+ReLU -------
__global__ void gxfinal_kernel(const float* __restrict__ gamma, const float* __restrict__ beta) {
    int idx = blockIdx.x * 256 + threadIdx.x;   // 16 blocks x 256 = 4096
    int j = idx & 63;
    float m   = g_sum[2 * HID + j] * (1.0f / N_NODES);
    float var = g_sum[3 * HID + j] * (1.0f / N_NODES) - m * m;
    float inv = rsqrtf(var + EPS);
    float sc = inv * gamma[j];
    float sh = beta[j] - m * sc;
    float v = (sc >= 0.f) ? decf(g_mxe[idx]) : decf(g_mne[idx]);
    g_gx[idx] = __float_as_uint(fmaxf(fmaf(v, sc, sh), 0.f));
}

// ---------------- head: speed enc + route enc + MLP (one block, 64 thr) -----
__global__ void head_kernel(const float* __restrict__ speed, const float* __restrict__ route,
                            const float* __restrict__ sw, const float* __restrict__ sb,
                            const float* __restrict__ sg, const float* __restrict__ sbe,
                            const float* __restrict__ cw, const float* __restrict__ cb,
                            const float* __restrict__ rg, const float* __restrict__ rbe,
                            const float* __restrict__ rw, const float* __restrict__ rb,
                            const float* __restrict__ ow1, const float* __restrict__ ob1,
                            const float* __restrict__ og, const float* __restrict__ obe,
                            const float* __restrict__ ow2, const float* __restrict__ ob2,
                            float* __restrict__ out) {
    int b = threadIdx.x;  // 64 threads
    __shared__ float s_v[NB][4];
    __shared__ float s_rc[NB][10];
    __shared__ float s_o1[NB][16];
    __shared__ float s_m[16], s_i[16];

    float sp = speed[b];
    #pragma unroll
    for (int j = 0; j < 4; j++) s_v[b][j] = sp * sw[j] + sb[j];

    const float* rt = route + b * 20;
    #pragma unroll
    for (int t = 0; t < 10; t++) {
        float a = cb[0];
        #pragma unroll
        for (int k = 0; k < 3; k++) {
            int tau = t + k - 1;
            if (tau >= 0 && tau < 10) {
                a += rt[tau * 2 + 0] * cw[k];
                a += rt[tau * 2 + 1] * cw[3 + k];
            }
        }
        s_rc[b][t] = a;
    }
    __syncthreads();

    if (b < 4) {
        float s = 0.f, q = 0.f;
        for (int i = 0; i < NB; i++) { float v = s_v[i][b]; s += v; q += v * v; }
        float m = s / NB, var = q / NB - m * m;
        s_m[b] = m; s_i[b] = rsqrtf(var + EPS);
    }
    if (b == 8) {
        float s = 0.f, q = 0.f;
        for (int i = 0; i < NB; i++)
            for (int t = 0; t < 10; t++) { float v = s_rc[i][t]; s += v; q += v * v; }
        float m = s / 640.f, var = q / 640.f - m * m;
        s_m[8] = m; s_i[8] = rsqrtf(var + EPS);
    }
    __syncthreads();

    float vj[4];
    #pragma unroll
    for (int j = 0; j < 4; j++)
        vj[j] = fmaxf((s_v[b][j] - s_m[j]) * s_i[j] * sg[j] + sbe[j], 0.f);

    float rcn[10];
    #pragma unroll
    for (int t = 0; t < 10; t++)
        rcn[t] = fmaxf((s_rc[b][t] - s_m[8]) * s_i[8] * rg[0] + rbe[0], 0.f);

    float rj[4];
    #pragma unroll
    for (int j = 0; j < 4; j++) {
        float a = rb[j];
        #pragma unroll
        for (int t = 0; t < 10; t++) a += rcn[t] * rw[t * 4 + j];
        rj[j] = a;
    }

    #pragma unroll
    for (int j = 0; j < 16; j++) {
        float a = ob1[j];
        for (int k = 0; k < HID; k++)
            a += __uint_as_float(g_gx[b * HID + k]) * ow1[k * 16 + j];
        #pragma unroll
        for (int k = 0; k < 4; k++) a += vj[k] * ow1[(HID + k) * 16 + j];
        #pragma unroll
        for (int k = 0; k < 4; k++) a += rj[k] * ow1[(HID + 4 + k) * 16 + j];
        s_o1[b][j] = a;
    }
    __syncthreads();
    if (b < 16) {
        float s = 0.f, q = 0.f;
        for (int i = 0; i < NB; i++) { float v = s_o1[i][b]; s += v; q += v * v; }
        float m = s / NB, var = q / NB - m * m;
        s_m[b] = m; s_i[b] = rsqrtf(var + EPS);
    }
    __syncthreads();
    float on[16];
    #pragma unroll
    for (int j = 0; j < 16; j++)
        on[j] = fmaxf((s_o1[b][j] - s_m[j]) * s_i[j] * og[j] + obe[j], 0.f);
    #pragma unroll
    for (int a = 0; a < 5; a++) {
        float o = ob2[a];
        #pragma unroll
        for (int j = 0; j < 16; j++) o += on[j] * ow2[j * 5 + a];
        out[b * 5 + a] = o;
    }
}

// ---------------------------------------------------------------------------
extern "C" void kernel_launch(void* const* d_in, const int* in_sizes, int n_in,
                              void* d_out, int out_size) {
    const float* x    = (const float*)d_in[0];
    const int*   ei   = (const int*)d_in[1];
    const float* ew   = (const float*)d_in[2];
    const int*   bidx = (const int*)d_in[3];
    const float* speed = (const float*)d_in[4];
    const float* route = (const float*)d_in[5];
    const float* W1 = (const float*)d_in[6];
    const float* g1 = (const float*)d_in[8];
    const float* be1 = (const float*)d_in[9];
    const float* W2 = (const float*)d_in[10];
    const float* g2 = (const float*)d_in[12];
    const float* be2 = (const float*)d_in[13];
    const float* sw  = (const float*)d_in[14];
    const float* sb  = (const float*)d_in[15];
    const float* sg  = (const float*)d_in[16];
    const float* sbe = (const float*)d_in[17];
    const float* cw  = (const float*)d_in[18];
    const float* cb  = (const float*)d_in[19];
    const float* rg  = (const float*)d_in[20];
    const float* rbe = (const float*)d_in[21];
    const float* rw  = (const float*)d_in[22];
    const float* rb  = (const float*)d_in[23];
    const float* ow1 = (const float*)d_in[24];
    const float* ob1 = (const float*)d_in[25];
    const float* og  = (const float*)d_in[26];
    const float* obe = (const float*)d_in[27];
    const float* ow2 = (const float*)d_in[28];
    const float* ob2 = (const float*)d_in[29];
    float* out = (float*)d_out;

    const int* row = ei;            // edge_index[0]
    const int* col = ei + N_EDGES;  // edge_index[1]

    // one-time infra objects (identical recorded work on every call)
    static cudaStream_t sB = 0;
    static cudaEvent_t evFork = 0, evJoin = 0;
    if (sB == 0) {
        cudaStreamCreateWithFlags(&sB, cudaStreamNonBlocking);
        cudaEventCreateWithFlags(&evFork, cudaEventDisableTiming);
        cudaEventCreateWithFlags(&evJoin, cudaEventDisableTiming);
    }

    // fork: gemm1 (independent of CSR build) runs on side stream
    cudaEventRecord(evFork, 0);
    cudaStreamWaitEvent(sB, evFork, 0);
    gemm1_kernel<<<(N_NODES + 63) / 64, 256, 0, sB>>>(x, W1);
    cudaEventRecord(evJoin, sB);

    // main stream: CSR build chain
    init_kernel<<<(N_NODES + 255) / 256, 256>>>();
    deg_kernel<<<(N_EDGES + 255) / 256, 256>>>(col, ew);
    scan1_kernel<<<NBLK, 256>>>();
    scan3_kernel<<<NBLK, 256>>>();
    fill_kernel<<<(N_EDGES + 255) / 256, 256>>>(row, col, ew);

    // join: gather(0) needs both branches
    cudaStreamWaitEvent(0, evJoin, 0);
    gather_kernel<<<N_NODES / 16, 256>>>(0, bidx);
    bnprep_kernel<<<1, 64>>>(g1, be1);

    gemm2_kernel<<<(N_NODES + 63) / 64, 256>>>(W2);
    gather_kernel<<<N_NODES / 16, 256>>>(1, bidx);
    gxfinal_kernel<<<16, 256>>>(g2, be2);

    head_kernel<<<1, 64>>>(speed, route, sw, sb, sg, sbe, cw, cb, rg, rbe,
                           rw, rb, ow1, ob1, og, obe, ow2, ob2, out);
}